// round 17
// baseline (speedup 1.0000x reference)
#include <cuda_runtime.h>
#include <cuda_bf16.h>
#include <math.h>

// ---------------- static scratch (no allocations allowed) ----------------
#define MAXN 50176

__device__ __align__(16) __nv_bfloat16 g_xl[MAXN * 128];
__device__ __align__(16) __nv_bfloat16 g_xr[MAXN * 128];
__device__ __align__(16) __nv_bfloat16 g_acc[MAXN * 128];
__device__ float g_denom[MAXN];
__device__ float g_pool[128];
__device__ unsigned g_arrive;
__device__ volatile int g_flag;
__device__ unsigned g_ticket;

__device__ __forceinline__ unsigned packbf2(float a, float b) {
    __nv_bfloat162 h = __float22bfloat162_rn(make_float2(a, b));
    return *(unsigned*)&h;
}

__device__ __forceinline__ void mma_bf16(float* c, const unsigned* a, unsigned b0, unsigned b1) {
    asm volatile(
        "mma.sync.aligned.m16n8k16.row.col.f32.bf16.bf16.f32 "
        "{%0,%1,%2,%3}, {%4,%5,%6,%7}, {%8,%9}, {%0,%1,%2,%3};\n"
        : "+f"(c[0]), "+f"(c[1]), "+f"(c[2]), "+f"(c[3])
        : "r"(a[0]), "r"(a[1]), "r"(a[2]), "r"(a[3]), "r"(b0), "r"(b1));
}

// ---------------- GEMM: 4 warps x (64M x 64N), full-K resident (frozen) ----------------
#define XS_STRIDE 76
#define WS_OFF    (128 * XS_STRIDE)
#define GEMM_SMEM ((WS_OFF + 64 * 132) * 4)

__device__ __forceinline__ void store_xq(unsigned* xsbuf, int rr, int c4, float4 v) {
    unsigned* row = xsbuf + rr * XS_STRIDE;
    int g2 = c4 >> 2, m = c4 & 3;
    int p0 = 2 * m, p1 = p0 + 1;
    int pos0 = ((p0 & 3) << 1) + (p0 >> 2);
    int pos1 = ((p1 & 3) << 1) + (p1 >> 2);
    row[g2 * 8 + pos0] = packbf2(v.x, v.y);
    row[g2 * 8 + pos1] = packbf2(v.z, v.w);
}

__global__ __launch_bounds__(128, 2) void gemm_kernel(
    const float* __restrict__ x,
    const float* __restrict__ Wl, const float* __restrict__ bl,
    const float* __restrict__ Wr, const float* __restrict__ br,
    int n)
{
    extern __shared__ unsigned dsm[];
    unsigned* wsf = dsm + WS_OFF;

    int row0 = blockIdx.x * 128;
    int t    = blockIdx.y;
    const float* W = t ? Wr : Wl;
    const float* b = t ? br : bl;
    __nv_bfloat16* outp = t ? g_xr : g_xl;

    int tid  = threadIdx.x;
    int lane = tid & 31;
    int wid  = tid >> 5;
    int wm   = wid & 1;
    int wn   = wid >> 1;

    if (t == 0) {
        uint4 z = make_uint4(0u, 0u, 0u, 0u);
        uint4* accp = (uint4*)(g_acc + (size_t)row0 * 128);
#pragma unroll
        for (int i = 0; i < 16; i++) accp[tid + i * 128] = z;
        g_denom[row0 + tid] = 0.0f;
        if (blockIdx.x == 0) {
            g_pool[tid] = 0.0f;
            if (tid == 0) { g_ticket = 0u; g_arrive = 0u; g_flag = 0; }
        }
    }

#pragma unroll
    for (int i = 0; i < 16; i++) {
        int idx = tid + i * 128;
        int kp = idx >> 5, c4 = idx & 31;
        int n0 = c4 * 4;
        float4 v0 = *(const float4*)(W + (size_t)(2 * kp)     * 128 + n0);
        float4 v1 = *(const float4*)(W + (size_t)(2 * kp + 1) * 128 + n0);
        const float* a0 = &v0.x;
        const float* a1 = &v1.x;
#pragma unroll
        for (int j = 0; j < 4; j++) {
            int nn = n0 + j;
            int pos = ((nn >> 6) << 6) + ((nn & 7) << 3) + ((nn & 63) >> 3);
            wsf[kp * 132 + pos] = packbf2(a0[j], a1[j]);
        }
    }

#pragma unroll
    for (int i = 0; i < 32; i++) {
        int idx = tid + i * 128;
        int rr = idx >> 5, c4 = idx & 31;
        float4 v = make_float4(0.f, 0.f, 0.f, 0.f);
        int gr = row0 + rr;
        if (gr < n) v = *(const float4*)(x + (size_t)gr * 128 + c4 * 4);
        store_xq(dsm, rr, c4, v);
    }
    __syncthreads();

    float c[32][4];
#pragma unroll
    for (int i = 0; i < 32; i++)
#pragma unroll
        for (int j = 0; j < 4; j++) c[i][j] = 0.0f;

    int q = lane & 3, r = lane >> 2;

#pragma unroll
    for (int g2 = 0; g2 < 8; g2++) {
        unsigned a[4][4];
#pragma unroll
        for (int mt = 0; mt < 4; mt++) {
            int rowA = wm * 64 + mt * 16 + r;
            uint2 lo = *(uint2*)&dsm[rowA * XS_STRIDE + g2 * 8 + 2 * q];
            uint2 hi = *(uint2*)&dsm[(rowA + 8) * XS_STRIDE + g2 * 8 + 2 * q];
            a[mt][0] = lo.x; a[mt][2] = lo.y;
            a[mt][1] = hi.x; a[mt][3] = hi.y;
        }
        int kb = g2 * 8 + q;
        uint4 b0a = *(uint4*)&wsf[kb * 132 + wn * 64 + r * 8];
        uint4 b0b = *(uint4*)&wsf[kb * 132 + wn * 64 + r * 8 + 4];
        uint4 b1a = *(uint4*)&wsf[(kb + 4) * 132 + wn * 64 + r * 8];
        uint4 b1b = *(uint4*)&wsf[(kb + 4) * 132 + wn * 64 + r * 8 + 4];
        unsigned b0r[8] = {b0a.x, b0a.y, b0a.z, b0a.w, b0b.x, b0b.y, b0b.z, b0b.w};
        unsigned b1r[8] = {b1a.x, b1a.y, b1a.z, b1a.w, b1b.x, b1b.y, b1b.z, b1b.w};
#pragma unroll
        for (int mt = 0; mt < 4; mt++)
#pragma unroll
            for (int nt = 0; nt < 8; nt++)
                mma_bf16(c[mt * 8 + nt], a[mt], b0r[nt], b1r[nt]);
    }

#pragma unroll
    for (int mt = 0; mt < 4; mt++) {
#pragma unroll
        for (int nt = 0; nt < 8; nt++) {
            int col = wn * 64 + nt * 8 + 2 * q;
            float2 bb = *(const float2*)(b + col);
            int grow = row0 + wm * 64 + mt * 16 + r;
            float* cc = c[mt * 8 + nt];
            if (grow < n) {
                __nv_bfloat162 o = __float22bfloat162_rn(
                    make_float2(cc[0] + bb.x, cc[1] + bb.y));
                *(__nv_bfloat162*)(outp + (size_t)grow * 128 + col) = o;
            }
            if (grow + 8 < n) {
                __nv_bfloat162 o = __float22bfloat162_rn(
                    make_float2(cc[2] + bb.x, cc[3] + bb.y));
                *(__nv_bfloat162*)(outp + (size_t)(grow + 8) * 128 + col) = o;
            }
        }
    }
}

// ---------------- persistent: edges -> grid barrier -> node pool -> head ----------------
__device__ __forceinline__ float lrelu(float v) { return v > 0.f ? v : 0.2f * v; }

__global__ __launch_bounds__(256, 4) void edge_node_kernel(
    const int* __restrict__ ei, const float* __restrict__ att,
    const float* __restrict__ bias1,
    const float* __restrict__ gamma, const float* __restrict__ beta,
    const float* __restrict__ mean,  const float* __restrict__ var,
    const float* __restrict__ Wc,    const float* __restrict__ bc,
    float* __restrict__ out, int E, int TE, int n)
{
    int tid  = threadIdx.x;
    int lane = tid & 31;
    int wib  = tid >> 5;
    int h    = lane >> 4;
    int l16  = lane & 15;

    // ---- phase 1: edges (half-warp per edge, 8 dims/lane, 8 edges/warp) ----
    float4 a0 = *(const float4*)(att + l16 * 8);
    float4 a1 = *(const float4*)(att + l16 * 8 + 4);
    float av[8] = {a0.x, a0.y, a0.z, a0.w, a1.x, a1.y, a1.z, a1.w};

    int gw = blockIdx.x * 8 + wib;
    int NW = gridDim.x * 8;

    for (int base = gw * 8; base < TE; base += NW * 8) {
        int s[4], d[4];
        bool ok[4];
#pragma unroll
        for (int p = 0; p < 4; p++) {
            int e0 = base + 2 * p;         // pair start
            int e  = e0 + h;
            ok[p] = (e < TE);
            if (!ok[p]) { s[p] = 0; d[p] = 0; }
            else if (e0 + 1 < E) {         // whole pair inside edge list: int2 loads
                int2 sp2 = __ldg((const int2*)(ei + e0));
                int2 dp2 = __ldg((const int2*)(ei + E + e0));
                s[p] = h ? sp2.y : sp2.x;
                d[p] = h ? dp2.y : dp2.x;
            } else if (e < E) { s[p] = __ldg(ei + e); d[p] = __ldg(ei + E + e); }
            else { s[p] = d[p] = e - E; }
        }

        uint4 xlu[4], xru[4];
#pragma unroll
        for (int p = 0; p < 4; p++) {
            xlu[p] = *(const uint4*)(g_xl + (size_t)s[p] * 128 + l16 * 8);
            xru[p] = *(const uint4*)(g_xr + (size_t)d[p] * 128 + l16 * 8);
        }

        float xl[4][8], v[4];
#pragma unroll
        for (int p = 0; p < 4; p++) {
            const unsigned* lu = &xlu[p].x;
            const unsigned* ru = &xru[p].x;
            float acc = 0.0f;
#pragma unroll
            for (int j = 0; j < 4; j++) {
                float2 lf = __bfloat1622float2(*(__nv_bfloat162*)&lu[j]);
                float2 rf = __bfloat1622float2(*(__nv_bfloat162*)&ru[j]);
                xl[p][2 * j + 0] = lf.x;
                xl[p][2 * j + 1] = lf.y;
                acc += av[2 * j + 0] * lrelu(lf.x + rf.x);
                acc += av[2 * j + 1] * lrelu(lf.y + rf.y);
            }
            v[p] = acc;
        }

#pragma unroll
        for (int o = 8; o; o >>= 1) {
#pragma unroll
            for (int p = 0; p < 4; p++)
                v[p] += __shfl_xor_sync(0xffffffffu, v[p], o);
        }

#pragma unroll
        for (int p = 0; p < 4; p++) {
            if (!ok[p]) continue;
            float wgt = __expf(v[p]);
            if (l16 == 0) {
                asm volatile("red.global.add.f32 [%0], %1;"
                             :: "l"(g_denom + d[p]), "f"(wgt) : "memory");
            }
            unsigned q0 = packbf2(wgt * xl[p][0], wgt * xl[p][1]);
            unsigned q1 = packbf2(wgt * xl[p][2], wgt * xl[p][3]);
            unsigned q2 = packbf2(wgt * xl[p][4], wgt * xl[p][5]);
            unsigned q3 = packbf2(wgt * xl[p][6], wgt * xl[p][7]);
            __nv_bfloat16* dstp = g_acc + (size_t)d[p] * 128 + l16 * 8;
            asm volatile("red.global.add.noftz.v4.bf16x2 [%0], {%1, %2, %3, %4};"
                         :: "l"(dstp), "r"(q0), "r"(q1), "r"(q2), "r"(q3) : "memory");
        }
    }

    // ---- grid barrier (all blocks resident by construction) ----
    __syncthreads();
    if (tid == 0) {
        __threadfence();
        unsigned prev = atomicAdd(&g_arrive, 1u);
        if (prev == gridDim.x - 1) g_flag = 1;
        while (g_flag == 0) __nanosleep(64);
    }
    __syncthreads();
    __threadfence();

    // ---- phase 2: node pool (16 nodes/block-iter, 16 lanes x 8 dims) ----
    int slot = tid >> 4;
    float p8[8];
#pragma unroll
    for (int j = 0; j < 8; j++) p8[j] = 0.0f;

    for (int r0 = blockIdx.x * 16; r0 < n; r0 += gridDim.x * 16) {
        int r = r0 + slot;
        if (r < n) {
            uint4 u = *(const uint4*)(g_acc + (size_t)r * 128 + l16 * 8);
            float inv = 1.0f / g_denom[r];
            const unsigned* uu = &u.x;
#pragma unroll
            for (int j = 0; j < 4; j++) {
                float2 f = __bfloat1622float2(*(__nv_bfloat162*)&uu[j]);
                p8[2 * j + 0] += f.x * inv;
                p8[2 * j + 1] += f.y * inv;
            }
        }
    }

    __shared__ float sp[16][128];
#pragma unroll
    for (int j = 0; j < 8; j++) sp[slot][l16 * 8 + j] = p8[j];
    __syncthreads();
    if (tid < 128) {
        float s = 0.0f;
#pragma unroll
        for (int s16 = 0; s16 < 16; s16++) s += sp[s16][tid];
        atomicAdd(&g_pool[tid], s);
    }
    __threadfence();

    // ---- phase 3: ticketed head ----
    __shared__ unsigned ticket;
    if (tid == 0) ticket = atomicAdd(&g_ticket, 1u);
    __syncthreads();
    if (ticket != gridDim.x - 1) return;

    __shared__ float gsh[128];
    __shared__ float lg[5];
    if (tid < 128) {
        float scd = gamma[tid] * rsqrtf(var[tid] + 1e-5f);
        float shd = beta[tid] - mean[tid] * scd;
        gsh[tid] = (__ldcg(&g_pool[tid]) / (float)n + bias1[tid]) * scd + shd;
    }
    __syncthreads();
    if (tid < 5) {
        float s = bc[tid];
#pragma unroll
        for (int k = 0; k < 128; k++) s += gsh[k] * Wc[k * 5 + tid];
        lg[tid] = s;
    }
    __syncthreads();
    if (tid == 0) {
        float m = lg[0];
        for (int i = 1; i < 5; i++) m = fmaxf(m, lg[i]);
        float e[5], den = 0.f;
        for (int i = 0; i < 5; i++) { e[i] = expf(lg[i] - m); den += e[i]; }
        for (int i = 0; i < 5; i++) out[i] = e[i] / den;
    }
}

// ---------------- launcher ----------------
extern "C" void kernel_launch(void* const* d_in, const int* in_sizes, int n_in,
                              void* d_out, int out_size)
{
    const float* x     = (const float*)d_in[0];
    const int*   ei    = (const int*)d_in[1];
    const float* Wl    = (const float*)d_in[2];
    const float* bl    = (const float*)d_in[3];
    const float* Wr    = (const float*)d_in[4];
    const float* br    = (const float*)d_in[5];
    const float* att   = (const float*)d_in[6];
    const float* bias1 = (const float*)d_in[7];
    const float* gam   = (const float*)d_in[8];
    const float* bet   = (const float*)d_in[9];
    const float* mea   = (const float*)d_in[10];
    const float* var   = (const float*)d_in[11];
    const float* Wc    = (const float*)d_in[12];
    const float* bc    = (const float*)d_in[13];
    float* out = (float*)d_out;

    int n  = in_sizes[0] / 128;
    int E  = in_sizes[1] / 2;
    int TE = E + n;

    static int NB = 0;
    if (!NB) {
        cudaFuncSetAttribute(gemm_kernel,
                             cudaFuncAttributeMaxDynamicSharedMemorySize, GEMM_SMEM);
        int dev = 0, sms = 148, bpm = 1;
        cudaGetDevice(&dev);
        cudaDeviceGetAttribute(&sms, cudaDevAttrMultiProcessorCount, dev);
        cudaOccupancyMaxActiveBlocksPerMultiprocessor(&bpm, edge_node_kernel, 256, 0);
        if (bpm < 1) bpm = 1;
        NB = sms * bpm;
        if (NB > 2048) NB = 2048;
    }

    dim3 gg((n + 127) / 128, 2);
    gemm_kernel<<<gg, 128, GEMM_SMEM>>>(x, Wl, bl, Wr, br, n);

    edge_node_kernel<<<NB, 256>>>(ei, att, bias1, gam, bet, mea, var, Wc, bc,
                                  out, E, TE, n);
}